// round 1
// baseline (speedup 1.0000x reference)
#include <cuda_runtime.h>
#include <cuda_bf16.h>
#include <math.h>

#define N_NODES 50000
#define NE      800000
#define EPRIME  850000            // NE + N_NODES (self loops appended)
#define HID     256               // = H*D
#define IN_DIM  1280

// ---------------- device scratch (no allocs allowed) ----------------
__device__ float    g_h0[N_NODES * HID];
__device__ float    g_h1[N_NODES * HID];
__device__ float    g_h2[N_NODES * HID];
__device__ float    g_xl[N_NODES * HID];
__device__ float    g_xr[N_NODES * HID];
__device__ float    g_agg[N_NODES * HID];
__device__ float    g_logits[(size_t)EPRIME * 4];
__device__ unsigned g_m[N_NODES * 4];
__device__ float    g_denom[N_NODES * 4];

// monotone float<->uint key for atomicMax over floats
__device__ __forceinline__ unsigned fkey(float f) {
    unsigned u = __float_as_uint(f);
    return (u & 0x80000000u) ? ~u : (u | 0x80000000u);
}
__device__ __forceinline__ float funkey(unsigned u) {
    return (u & 0x80000000u) ? __uint_as_float(u ^ 0x80000000u) : __uint_as_float(~u);
}

// ---------------- generic fp32 GEMM: C = A[M,K] @ B[K,Nc] + bias ----------------
// BM=BN=128, BK=8, 256 threads, 8x8 per thread. K % 8 == 0, Nc % 128 == 0.
__global__ __launch_bounds__(256) void sgemm_bias(
    const float* __restrict__ A, const float* __restrict__ B,
    const float* __restrict__ bias, float* __restrict__ C,
    int M, int K, int Nc)
{
    __shared__ float As[8][128];
    __shared__ float Bs[8][128];
    int tid = threadIdx.x;
    int m0 = blockIdx.y * 128, n0 = blockIdx.x * 128;
    int tx = tid & 15, ty = tid >> 4;

    float acc[8][8];
    #pragma unroll
    for (int i = 0; i < 8; i++)
        #pragma unroll
        for (int j = 0; j < 8; j++) acc[i][j] = 0.f;

    int aRow = tid >> 1;          // 0..127
    int aCol = (tid & 1) * 4;     // 0 or 4
    int bRow = tid >> 5;          // 0..7
    int bCol = (tid & 31) * 4;    // 0..124

    for (int k0 = 0; k0 < K; k0 += 8) {
        float4 av = make_float4(0.f, 0.f, 0.f, 0.f);
        int gr = m0 + aRow;
        if (gr < M) av = *(const float4*)(A + (size_t)gr * K + k0 + aCol);
        As[aCol + 0][aRow] = av.x;
        As[aCol + 1][aRow] = av.y;
        As[aCol + 2][aRow] = av.z;
        As[aCol + 3][aRow] = av.w;
        float4 bv = *(const float4*)(B + (size_t)(k0 + bRow) * Nc + n0 + bCol);
        *(float4*)&Bs[bRow][bCol] = bv;
        __syncthreads();
        #pragma unroll
        for (int kk = 0; kk < 8; kk++) {
            float a[8], b[8];
            *(float4*)&a[0] = *(const float4*)&As[kk][ty * 8];
            *(float4*)&a[4] = *(const float4*)&As[kk][ty * 8 + 4];
            *(float4*)&b[0] = *(const float4*)&Bs[kk][tx * 8];
            *(float4*)&b[4] = *(const float4*)&Bs[kk][tx * 8 + 4];
            #pragma unroll
            for (int i = 0; i < 8; i++)
                #pragma unroll
                for (int j = 0; j < 8; j++) acc[i][j] += a[i] * b[j];
        }
        __syncthreads();
    }

    float bb[8];
    #pragma unroll
    for (int j = 0; j < 8; j++) bb[j] = bias[n0 + tx * 8 + j];
    #pragma unroll
    for (int i = 0; i < 8; i++) {
        int r = m0 + ty * 8 + i;
        if (r < M) {
            float* pc = C + (size_t)r * Nc + n0 + tx * 8;
            #pragma unroll
            for (int j = 0; j < 8; j++) pc[j] = acc[i][j] + bb[j];
        }
    }
}

// ---------------- per-layer init ----------------
__global__ void init_layer_kernel(float* __restrict__ agg, float* __restrict__ denom,
                                  unsigned* __restrict__ m)
{
    int i = blockIdx.x * blockDim.x + threadIdx.x;
    if (i < N_NODES * HID) agg[i] = 0.f;
    if (i < N_NODES * 4) { denom[i] = 0.f; m[i] = 0u; }
}

// ---------------- edge logits + segment max (warp per edge) ----------------
__global__ __launch_bounds__(256) void edge_logits_kernel(
    const float* __restrict__ xl, const float* __restrict__ xr,
    const int* __restrict__ ei, const float* __restrict__ att,
    float* __restrict__ logits, unsigned* __restrict__ m)
{
    int w = (blockIdx.x * 256 + threadIdx.x) >> 5;
    int lane = threadIdx.x & 31;
    if (w >= EPRIME) return;
    int s, d;
    if (w < NE) { s = ei[w]; d = ei[NE + w]; } else { s = w - NE; d = s; }
    const float4* pl = (const float4*)(xl + (size_t)s * HID) + lane * 2;
    const float4* pr = (const float4*)(xr + (size_t)d * HID) + lane * 2;
    const float4* pa = (const float4*)att + lane * 2;
    float acc = 0.f;
    #pragma unroll
    for (int q = 0; q < 2; q++) {
        float4 l = pl[q], r = pr[q], a = pa[q];
        float v;
        v = l.x + r.x; v = v > 0.f ? v : 0.2f * v; acc += v * a.x;
        v = l.y + r.y; v = v > 0.f ? v : 0.2f * v; acc += v * a.y;
        v = l.z + r.z; v = v > 0.f ? v : 0.2f * v; acc += v * a.z;
        v = l.w + r.w; v = v > 0.f ? v : 0.2f * v; acc += v * a.w;
    }
    // lane handles elements [lane*8, lane*8+8) -> head = lane>>3; reduce within 8-lane group
    acc += __shfl_xor_sync(0xffffffffu, acc, 1);
    acc += __shfl_xor_sync(0xffffffffu, acc, 2);
    acc += __shfl_xor_sync(0xffffffffu, acc, 4);
    if ((lane & 7) == 0) {
        int h = lane >> 3;
        logits[(size_t)w * 4 + h] = acc;
        atomicMax(&m[(size_t)d * 4 + h], fkey(acc));
    }
}

// ---------------- exp(logit - max) + segment sum (thread per edge*head) ----------------
__global__ void edge_exp_kernel(const int* __restrict__ ei,
                                const float* __restrict__ logits,
                                const unsigned* __restrict__ m,
                                float* __restrict__ denom,
                                float* __restrict__ a_out)
{
    long long i = (long long)blockIdx.x * blockDim.x + threadIdx.x;
    if (i >= (long long)EPRIME * 4) return;
    int e = (int)(i >> 2), h = (int)(i & 3);
    int d = (e < NE) ? ei[NE + e] : e - NE;
    float mm = funkey(m[(size_t)d * 4 + h]);
    float a = expf(logits[i] - mm);
    atomicAdd(&denom[(size_t)d * 4 + h], a);
    a_out[i] = a;
}

// ---------------- alpha + weighted scatter (warp per edge) ----------------
__global__ __launch_bounds__(256) void edge_aggregate_kernel(
    const float* __restrict__ xl, const int* __restrict__ ei,
    const float* __restrict__ denom, float* __restrict__ alpha_out,
    float* __restrict__ out)
{
    int w = (blockIdx.x * 256 + threadIdx.x) >> 5;
    int lane = threadIdx.x & 31;
    if (w >= EPRIME) return;
    int s, d;
    if (w < NE) { s = ei[w]; d = ei[NE + w]; } else { s = w - NE; d = s; }
    float4 av = *(const float4*)(alpha_out + (size_t)w * 4);   // all lanes load (broadcast)
    float4 dv = *(const float4*)(denom + (size_t)d * 4);
    float al4[4];
    al4[0] = av.x / (dv.x + 1e-16f);
    al4[1] = av.y / (dv.y + 1e-16f);
    al4[2] = av.z / (dv.z + 1e-16f);
    al4[3] = av.w / (dv.w + 1e-16f);
    if (lane == 0)
        *(float4*)(alpha_out + (size_t)w * 4) = make_float4(al4[0], al4[1], al4[2], al4[3]);
    float alpha = al4[lane >> 3];
    const float4* pl = (const float4*)(xl + (size_t)s * HID) + lane * 2;
    float* po = out + (size_t)d * HID + lane * 8;
    #pragma unroll
    for (int q = 0; q < 2; q++) {
        float4 v = pl[q];
        v.x *= alpha; v.y *= alpha; v.z *= alpha; v.w *= alpha;
        asm volatile("red.global.add.v4.f32 [%0], {%1,%2,%3,%4};"
                     :: "l"(po + q * 4), "f"(v.x), "f"(v.y), "f"(v.z), "f"(v.w)
                     : "memory");
    }
}

// ---------------- out = elu(agg + bias + residual) ----------------
__global__ void finalize_kernel(const float* __restrict__ agg, const float* __restrict__ bias,
                                const float* __restrict__ h_in, float* __restrict__ h_out)
{
    int i = blockIdx.x * blockDim.x + threadIdx.x;
    if (i >= N_NODES * HID) return;
    float v = agg[i] + bias[i & (HID - 1)] + h_in[i];
    h_out[i] = v > 0.f ? v : expm1f(v);
}

// ---------------- classifier: preds[n] = h[n] . W + b (warp per node) ----------------
__global__ __launch_bounds__(256) void clf_kernel(const float* __restrict__ h,
                                                  const float* __restrict__ W,
                                                  const float* __restrict__ b,
                                                  float* __restrict__ preds)
{
    int w = (blockIdx.x * 256 + threadIdx.x) >> 5;
    int lane = threadIdx.x & 31;
    if (w >= N_NODES) return;
    const float4* ph = (const float4*)(h + (size_t)w * HID) + lane * 2;
    const float4* pw = (const float4*)W + lane * 2;
    float acc = 0.f;
    #pragma unroll
    for (int q = 0; q < 2; q++) {
        float4 a = ph[q], c = pw[q];
        acc += a.x * c.x + a.y * c.y + a.z * c.z + a.w * c.w;
    }
    #pragma unroll
    for (int o = 16; o; o >>= 1) acc += __shfl_xor_sync(0xffffffffu, acc, o);
    if (lane == 0) preds[w] = acc + b[0];
}

// ---------------- host orchestration ----------------
extern "C" void kernel_launch(void* const* d_in, const int* in_sizes, int n_in,
                              void* d_out, int out_size)
{
    const float* x     = (const float*)d_in[0];
    const int*   ei    = (const int*)d_in[1];
    const float* enc_W = (const float*)d_in[2];
    const float* enc_b = (const float*)d_in[3];
    const float* Wl0   = (const float*)d_in[4];
    const float* bl0   = (const float*)d_in[5];
    const float* Wr0   = (const float*)d_in[6];
    const float* br0   = (const float*)d_in[7];
    const float* att0  = (const float*)d_in[8];
    const float* bias0 = (const float*)d_in[9];
    const float* Wl1   = (const float*)d_in[10];
    const float* bl1   = (const float*)d_in[11];
    const float* Wr1   = (const float*)d_in[12];
    const float* br1   = (const float*)d_in[13];
    const float* att1  = (const float*)d_in[14];
    const float* bias1 = (const float*)d_in[15];
    const float* clf_W = (const float*)d_in[16];
    const float* clf_b = (const float*)d_in[17];

    float* out    = (float*)d_out;
    float* preds  = out;
    float* alpha0 = out + N_NODES;
    float* alpha1 = alpha0 + (size_t)EPRIME * 4;

    float *h0, *h1, *h2, *xl, *xr, *agg, *logits, *denom; unsigned* m;
    cudaGetSymbolAddress((void**)&h0, g_h0);
    cudaGetSymbolAddress((void**)&h1, g_h1);
    cudaGetSymbolAddress((void**)&h2, g_h2);
    cudaGetSymbolAddress((void**)&xl, g_xl);
    cudaGetSymbolAddress((void**)&xr, g_xr);
    cudaGetSymbolAddress((void**)&agg, g_agg);
    cudaGetSymbolAddress((void**)&logits, g_logits);
    cudaGetSymbolAddress((void**)&denom, g_denom);
    cudaGetSymbolAddress((void**)&m, g_m);

    dim3 gemmGrid(HID / 128, (N_NODES + 127) / 128);
    int elemBlocks = (N_NODES * HID + 255) / 256;
    int edgeWarpBlocks = (EPRIME * 32 + 255) / 256;
    int edgeHeadBlocks = (EPRIME * 4 + 255) / 256;

    // encoder
    sgemm_bias<<<gemmGrid, 256>>>(x, enc_W, enc_b, h0, N_NODES, IN_DIM, HID);

    // ----- layer 0 -----
    sgemm_bias<<<gemmGrid, 256>>>(h0, Wl0, bl0, xl, N_NODES, HID, HID);
    sgemm_bias<<<gemmGrid, 256>>>(h0, Wr0, br0, xr, N_NODES, HID, HID);
    init_layer_kernel<<<elemBlocks, 256>>>(agg, denom, m);
    edge_logits_kernel<<<edgeWarpBlocks, 256>>>(xl, xr, ei, att0, logits, m);
    edge_exp_kernel<<<edgeHeadBlocks, 256>>>(ei, logits, m, denom, alpha0);
    edge_aggregate_kernel<<<edgeWarpBlocks, 256>>>(xl, ei, denom, alpha0, agg);
    finalize_kernel<<<elemBlocks, 256>>>(agg, bias0, h0, h1);

    // ----- layer 1 -----
    sgemm_bias<<<gemmGrid, 256>>>(h1, Wl1, bl1, xl, N_NODES, HID, HID);
    sgemm_bias<<<gemmGrid, 256>>>(h1, Wr1, br1, xr, N_NODES, HID, HID);
    init_layer_kernel<<<elemBlocks, 256>>>(agg, denom, m);
    edge_logits_kernel<<<edgeWarpBlocks, 256>>>(xl, xr, ei, att1, logits, m);
    edge_exp_kernel<<<edgeHeadBlocks, 256>>>(ei, logits, m, denom, alpha1);
    edge_aggregate_kernel<<<edgeWarpBlocks, 256>>>(xl, ei, denom, alpha1, agg);
    finalize_kernel<<<elemBlocks, 256>>>(agg, bias1, h1, h2);

    // classifier
    clf_kernel<<<(N_NODES * 32 + 255) / 256, 256>>>(h2, clf_W, clf_b, preds);
}

// round 2
// speedup vs baseline: 1.6202x; 1.6202x over previous
#include <cuda_runtime.h>
#include <cuda_bf16.h>
#include <math.h>
#include <stdint.h>

#define N_NODES 50000
#define NE      800000
#define EPRIME  850000            // NE + N_NODES (self loops appended)
#define HID     256               // = H*D
#define IN_DIM  1280

// ---------------- device scratch (no allocs allowed) ----------------
__device__ float    g_h0[N_NODES * HID];
__device__ float    g_h1[N_NODES * HID];
__device__ float    g_h2[N_NODES * HID];
__device__ float    g_xl[N_NODES * HID];
__device__ float    g_xr[N_NODES * HID];
__device__ float    g_agg[N_NODES * HID];
__device__ float    g_logits[(size_t)EPRIME * 4];
__device__ unsigned g_m[N_NODES * 4];
__device__ float    g_denom[N_NODES * 4];

// monotone float<->uint key for atomicMax over floats
__device__ __forceinline__ unsigned fkey(float f) {
    unsigned u = __float_as_uint(f);
    return (u & 0x80000000u) ? ~u : (u | 0x80000000u);
}
__device__ __forceinline__ float funkey(unsigned u) {
    return (u & 0x80000000u) ? __uint_as_float(u ^ 0x80000000u) : __uint_as_float(~u);
}

__device__ __forceinline__ uint32_t f2tf(float x) {
    uint32_t u;
    asm("cvt.rna.tf32.f32 %0, %1;" : "=r"(u) : "f"(x));
    return u;
}

// ---------------- TF32 tensor-core GEMM: C = A[M,K] @ B[K,Nc] + bias ----------------
// BM=BN=128, BK=16, 256 threads (8 warps), warp tile 64x32 via mma.m16n8k8.
// Requires K % 16 == 0, Nc % 128 == 0.
__global__ __launch_bounds__(256) void gemm_tf32_bias(
    const float* __restrict__ A, const float* __restrict__ B,
    const float* __restrict__ bias, float* __restrict__ C,
    int M, int K, int Nc)
{
    // As stored [m][k] with row stride 20 (conflict-free a-frag LDS)
    // Bs stored [k][n] with row stride 136 (conflict-free b-frag LDS)
    __shared__ uint32_t As[128][20];
    __shared__ uint32_t Bs[16][136];

    int tid = threadIdx.x;
    int wid = tid >> 5, lane = tid & 31;
    int warp_m = (wid & 1) * 64;   // 2 warps along M
    int warp_n = (wid >> 1) * 32;  // 4 warps along N
    int g = lane >> 2;             // 0..7
    int t4 = lane & 3;             // 0..3

    int m0 = blockIdx.y * 128, n0 = blockIdx.x * 128;

    float c[16][4];
    #pragma unroll
    for (int i = 0; i < 16; i++)
        #pragma unroll
        for (int j = 0; j < 4; j++) c[i][j] = 0.f;

    // global-load assignments
    int aRow = tid >> 1;           // 0..127
    int aK   = (tid & 1) * 8;      // 0 or 8
    int bRow = tid >> 4;           // 0..15
    int bCol = (tid & 15) * 8;     // 0..120

    for (int k0 = 0; k0 < K; k0 += 16) {
        // ---- stage A tile (cvt to tf32) ----
        {
            int gr = m0 + aRow;
            float4 v0 = make_float4(0.f, 0.f, 0.f, 0.f), v1 = v0;
            if (gr < M) {
                const float* pa = A + (size_t)gr * K + k0 + aK;
                v0 = *(const float4*)pa;
                v1 = *(const float4*)(pa + 4);
            }
            uint32_t* ps = &As[aRow][aK];
            ps[0] = f2tf(v0.x); ps[1] = f2tf(v0.y); ps[2] = f2tf(v0.z); ps[3] = f2tf(v0.w);
            ps[4] = f2tf(v1.x); ps[5] = f2tf(v1.y); ps[6] = f2tf(v1.z); ps[7] = f2tf(v1.w);
        }
        // ---- stage B tile ----
        {
            const float* pb = B + (size_t)(k0 + bRow) * Nc + n0 + bCol;
            float4 v0 = *(const float4*)pb;
            float4 v1 = *(const float4*)(pb + 4);
            uint32_t* ps = &Bs[bRow][bCol];
            ps[0] = f2tf(v0.x); ps[1] = f2tf(v0.y); ps[2] = f2tf(v0.z); ps[3] = f2tf(v0.w);
            ps[4] = f2tf(v1.x); ps[5] = f2tf(v1.y); ps[6] = f2tf(v1.z); ps[7] = f2tf(v1.w);
        }
        __syncthreads();

        #pragma unroll
        for (int ks = 0; ks < 16; ks += 8) {
            uint32_t a[4][4];
            #pragma unroll
            for (int i = 0; i < 4; i++) {
                int m = warp_m + i * 16;
                a[i][0] = As[m + g    ][ks + t4];
                a[i][1] = As[m + g + 8][ks + t4];
                a[i][2] = As[m + g    ][ks + t4 + 4];
                a[i][3] = As[m + g + 8][ks + t4 + 4];
            }
            uint32_t b[4][2];
            #pragma unroll
            for (int j = 0; j < 4; j++) {
                int n = warp_n + j * 8;
                b[j][0] = Bs[ks + t4    ][n + g];
                b[j][1] = Bs[ks + t4 + 4][n + g];
            }
            #pragma unroll
            for (int i = 0; i < 4; i++)
                #pragma unroll
                for (int j = 0; j < 4; j++) {
                    float* cc = c[i * 4 + j];
                    asm volatile(
                        "mma.sync.aligned.m16n8k8.row.col.f32.tf32.tf32.f32 "
                        "{%0,%1,%2,%3}, {%4,%5,%6,%7}, {%8,%9}, {%0,%1,%2,%3};"
                        : "+f"(cc[0]), "+f"(cc[1]), "+f"(cc[2]), "+f"(cc[3])
                        : "r"(a[i][0]), "r"(a[i][1]), "r"(a[i][2]), "r"(a[i][3]),
                          "r"(b[j][0]), "r"(b[j][1]));
                }
        }
        __syncthreads();
    }

    // ---- epilogue: add bias, store ----
    #pragma unroll
    for (int i = 0; i < 4; i++) {
        #pragma unroll
        for (int j = 0; j < 4; j++) {
            float* cc = c[i * 4 + j];
            int col = n0 + warp_n + j * 8 + t4 * 2;
            float b0 = bias[col], b1 = bias[col + 1];
            int r0 = m0 + warp_m + i * 16 + g;
            if (r0 < M) {
                float2* p = (float2*)(C + (size_t)r0 * Nc + col);
                *p = make_float2(cc[0] + b0, cc[1] + b1);
            }
            int r1 = r0 + 8;
            if (r1 < M) {
                float2* p = (float2*)(C + (size_t)r1 * Nc + col);
                *p = make_float2(cc[2] + b0, cc[3] + b1);
            }
        }
    }
}

// ---------------- per-layer init ----------------
__global__ void init_layer_kernel(float* __restrict__ agg, float* __restrict__ denom,
                                  unsigned* __restrict__ m)
{
    int i = blockIdx.x * blockDim.x + threadIdx.x;
    if (i < N_NODES * HID) agg[i] = 0.f;
    if (i < N_NODES * 4) { denom[i] = 0.f; m[i] = 0u; }
}

// ---------------- edge logits + segment max (warp per edge) ----------------
__global__ __launch_bounds__(256) void edge_logits_kernel(
    const float* __restrict__ xl, const float* __restrict__ xr,
    const int* __restrict__ ei, const float* __restrict__ att,
    float* __restrict__ logits, unsigned* __restrict__ m)
{
    int w = (blockIdx.x * 256 + threadIdx.x) >> 5;
    int lane = threadIdx.x & 31;
    if (w >= EPRIME) return;
    int s, d;
    if (w < NE) { s = ei[w]; d = ei[NE + w]; } else { s = w - NE; d = s; }
    const float4* pl = (const float4*)(xl + (size_t)s * HID) + lane * 2;
    const float4* pr = (const float4*)(xr + (size_t)d * HID) + lane * 2;
    const float4* pa = (const float4*)att + lane * 2;
    float acc = 0.f;
    #pragma unroll
    for (int q = 0; q < 2; q++) {
        float4 l = pl[q], r = pr[q], a = pa[q];
        float v;
        v = l.x + r.x; v = v > 0.f ? v : 0.2f * v; acc += v * a.x;
        v = l.y + r.y; v = v > 0.f ? v : 0.2f * v; acc += v * a.y;
        v = l.z + r.z; v = v > 0.f ? v : 0.2f * v; acc += v * a.z;
        v = l.w + r.w; v = v > 0.f ? v : 0.2f * v; acc += v * a.w;
    }
    acc += __shfl_xor_sync(0xffffffffu, acc, 1);
    acc += __shfl_xor_sync(0xffffffffu, acc, 2);
    acc += __shfl_xor_sync(0xffffffffu, acc, 4);
    if ((lane & 7) == 0) {
        int h = lane >> 3;
        logits[(size_t)w * 4 + h] = acc;
        atomicMax(&m[(size_t)d * 4 + h], fkey(acc));
    }
}

// ---------------- exp(logit - max) + segment sum (thread per edge*head) ----------------
__global__ void edge_exp_kernel(const int* __restrict__ ei,
                                const float* __restrict__ logits,
                                const unsigned* __restrict__ m,
                                float* __restrict__ denom,
                                float* __restrict__ a_out)
{
    long long i = (long long)blockIdx.x * blockDim.x + threadIdx.x;
    if (i >= (long long)EPRIME * 4) return;
    int e = (int)(i >> 2), h = (int)(i & 3);
    int d = (e < NE) ? ei[NE + e] : e - NE;
    float mm = funkey(m[(size_t)d * 4 + h]);
    float a = expf(logits[i] - mm);
    atomicAdd(&denom[(size_t)d * 4 + h], a);
    a_out[i] = a;
}

// ---------------- alpha + weighted scatter (warp per edge) ----------------
__global__ __launch_bounds__(256) void edge_aggregate_kernel(
    const float* __restrict__ xl, const int* __restrict__ ei,
    const float* __restrict__ denom, float* __restrict__ alpha_out,
    float* __restrict__ out)
{
    int w = (blockIdx.x * 256 + threadIdx.x) >> 5;
    int lane = threadIdx.x & 31;
    if (w >= EPRIME) return;
    int s, d;
    if (w < NE) { s = ei[w]; d = ei[NE + w]; } else { s = w - NE; d = s; }
    float4 av = *(const float4*)(alpha_out + (size_t)w * 4);
    float4 dv = *(const float4*)(denom + (size_t)d * 4);
    float al4[4];
    al4[0] = av.x / (dv.x + 1e-16f);
    al4[1] = av.y / (dv.y + 1e-16f);
    al4[2] = av.z / (dv.z + 1e-16f);
    al4[3] = av.w / (dv.w + 1e-16f);
    if (lane == 0)
        *(float4*)(alpha_out + (size_t)w * 4) = make_float4(al4[0], al4[1], al4[2], al4[3]);
    float alpha = al4[lane >> 3];
    const float4* pl = (const float4*)(xl + (size_t)s * HID) + lane * 2;
    float* po = out + (size_t)d * HID + lane * 8;
    #pragma unroll
    for (int q = 0; q < 2; q++) {
        float4 v = pl[q];
        v.x *= alpha; v.y *= alpha; v.z *= alpha; v.w *= alpha;
        asm volatile("red.global.add.v4.f32 [%0], {%1,%2,%3,%4};"
                     :: "l"(po + q * 4), "f"(v.x), "f"(v.y), "f"(v.z), "f"(v.w)
                     : "memory");
    }
}

// ---------------- out = elu(agg + bias + residual) ----------------
__global__ void finalize_kernel(const float* __restrict__ agg, const float* __restrict__ bias,
                                const float* __restrict__ h_in, float* __restrict__ h_out)
{
    int i = blockIdx.x * blockDim.x + threadIdx.x;
    if (i >= N_NODES * HID) return;
    float v = agg[i] + bias[i & (HID - 1)] + h_in[i];
    h_out[i] = v > 0.f ? v : expm1f(v);
}

// ---------------- classifier: preds[n] = h[n] . W + b (warp per node) ----------------
__global__ __launch_bounds__(256) void clf_kernel(const float* __restrict__ h,
                                                  const float* __restrict__ W,
                                                  const float* __restrict__ b,
                                                  float* __restrict__ preds)
{
    int w = (blockIdx.x * 256 + threadIdx.x) >> 5;
    int lane = threadIdx.x & 31;
    if (w >= N_NODES) return;
    const float4* ph = (const float4*)(h + (size_t)w * HID) + lane * 2;
    const float4* pw = (const float4*)W + lane * 2;
    float acc = 0.f;
    #pragma unroll
    for (int q = 0; q < 2; q++) {
        float4 a = ph[q], c = pw[q];
        acc += a.x * c.x + a.y * c.y + a.z * c.z + a.w * c.w;
    }
    #pragma unroll
    for (int o = 16; o; o >>= 1) acc += __shfl_xor_sync(0xffffffffu, acc, o);
    if (lane == 0) preds[w] = acc + b[0];
}

// ---------------- host orchestration ----------------
extern "C" void kernel_launch(void* const* d_in, const int* in_sizes, int n_in,
                              void* d_out, int out_size)
{
    const float* x     = (const float*)d_in[0];
    const int*   ei    = (const int*)d_in[1];
    const float* enc_W = (const float*)d_in[2];
    const float* enc_b = (const float*)d_in[3];
    const float* Wl0   = (const float*)d_in[4];
    const float* bl0   = (const float*)d_in[5];
    const float* Wr0   = (const float*)d_in[6];
    const float* br0   = (const float*)d_in[7];
    const float* att0  = (const float*)d_in[8];
    const float* bias0 = (const float*)d_in[9];
    const float* Wl1   = (const float*)d_in[10];
    const float* bl1   = (const float*)d_in[11];
    const float* Wr1   = (const float*)d_in[12];
    const float* br1   = (const float*)d_in[13];
    const float* att1  = (const float*)d_in[14];
    const float* bias1 = (const float*)d_in[15];
    const float* clf_W = (const float*)d_in[16];
    const float* clf_b = (const float*)d_in[17];

    float* out    = (float*)d_out;
    float* preds  = out;
    float* alpha0 = out + N_NODES;
    float* alpha1 = alpha0 + (size_t)EPRIME * 4;

    float *h0, *h1, *h2, *xl, *xr, *agg, *logits, *denom; unsigned* m;
    cudaGetSymbolAddress((void**)&h0, g_h0);
    cudaGetSymbolAddress((void**)&h1, g_h1);
    cudaGetSymbolAddress((void**)&h2, g_h2);
    cudaGetSymbolAddress((void**)&xl, g_xl);
    cudaGetSymbolAddress((void**)&xr, g_xr);
    cudaGetSymbolAddress((void**)&agg, g_agg);
    cudaGetSymbolAddress((void**)&logits, g_logits);
    cudaGetSymbolAddress((void**)&denom, g_denom);
    cudaGetSymbolAddress((void**)&m, g_m);

    dim3 gemmGrid(HID / 128, (N_NODES + 127) / 128);
    int elemBlocks = (N_NODES * HID + 255) / 256;
    int edgeWarpBlocks = (EPRIME * 32 + 255) / 256;
    int edgeHeadBlocks = (EPRIME * 4 + 255) / 256;

    // encoder
    gemm_tf32_bias<<<gemmGrid, 256>>>(x, enc_W, enc_b, h0, N_NODES, IN_DIM, HID);

    // ----- layer 0 -----
    gemm_tf32_bias<<<gemmGrid, 256>>>(h0, Wl0, bl0, xl, N_NODES, HID, HID);
    gemm_tf32_bias<<<gemmGrid, 256>>>(h0, Wr0, br0, xr, N_NODES, HID, HID);
    init_layer_kernel<<<elemBlocks, 256>>>(agg, denom, m);
    edge_logits_kernel<<<edgeWarpBlocks, 256>>>(xl, xr, ei, att0, logits, m);
    edge_exp_kernel<<<edgeHeadBlocks, 256>>>(ei, logits, m, denom, alpha0);
    edge_aggregate_kernel<<<edgeWarpBlocks, 256>>>(xl, ei, denom, alpha0, agg);
    finalize_kernel<<<elemBlocks, 256>>>(agg, bias0, h0, h1);

    // ----- layer 1 -----
    gemm_tf32_bias<<<gemmGrid, 256>>>(h1, Wl1, bl1, xl, N_NODES, HID, HID);
    gemm_tf32_bias<<<gemmGrid, 256>>>(h1, Wr1, br1, xr, N_NODES, HID, HID);
    init_layer_kernel<<<elemBlocks, 256>>>(agg, denom, m);
    edge_logits_kernel<<<edgeWarpBlocks, 256>>>(xl, xr, ei, att1, logits, m);
    edge_exp_kernel<<<edgeHeadBlocks, 256>>>(ei, logits, m, denom, alpha1);
    edge_aggregate_kernel<<<edgeWarpBlocks, 256>>>(xl, ei, denom, alpha1, agg);
    finalize_kernel<<<elemBlocks, 256>>>(agg, bias1, h1, h2);

    // classifier
    clf_kernel<<<(N_NODES * 32 + 255) / 256, 256>>>(h2, clf_W, clf_b, preds);
}

// round 3
// speedup vs baseline: 2.5746x; 1.5890x over previous
#include <cuda_runtime.h>
#include <cuda_bf16.h>
#include <math.h>
#include <stdint.h>

#define N_NODES 50000
#define NE      800000
#define EPRIME  850000            // NE + N_NODES (self loops appended)
#define HID     256               // = H*D
#define IN_DIM  1280

// ---------------- device scratch (no allocs allowed) ----------------
__device__ float    g_h0[N_NODES * HID];
__device__ float    g_h1[N_NODES * HID];
__device__ float    g_h2[N_NODES * HID];
__device__ float    g_xl[N_NODES * HID];
__device__ float    g_xr[N_NODES * HID];
__device__ float    g_logits[(size_t)EPRIME * 4];
__device__ float    g_mstat[N_NODES * 4];
__device__ float    g_dstat[N_NODES * 4];
__device__ int      g_deg[N_NODES];
__device__ int      g_cur[N_NODES];
__device__ int      g_off[N_NODES + 1];
__device__ int2     g_csr[EPRIME];          // .x = src node, .y = original edge id

__device__ __forceinline__ uint32_t f2tf(float x) {
    uint32_t u;
    asm("cvt.rna.tf32.f32 %0, %1;" : "=r"(u) : "f"(x));
    return u;
}

// ---------------- TF32 tensor-core GEMM: C = A[M,K] @ B[K,Nc] + bias ----------------
__global__ __launch_bounds__(256) void gemm_tf32_bias(
    const float* __restrict__ A, const float* __restrict__ B,
    const float* __restrict__ bias, float* __restrict__ C,
    int M, int K, int Nc)
{
    __shared__ uint32_t As[128][20];
    __shared__ uint32_t Bs[16][136];

    int tid = threadIdx.x;
    int wid = tid >> 5, lane = tid & 31;
    int warp_m = (wid & 1) * 64;
    int warp_n = (wid >> 1) * 32;
    int g = lane >> 2;
    int t4 = lane & 3;

    int m0 = blockIdx.y * 128, n0 = blockIdx.x * 128;

    float c[16][4];
    #pragma unroll
    for (int i = 0; i < 16; i++)
        #pragma unroll
        for (int j = 0; j < 4; j++) c[i][j] = 0.f;

    int aRow = tid >> 1;
    int aK   = (tid & 1) * 8;
    int bRow = tid >> 4;
    int bCol = (tid & 15) * 8;

    for (int k0 = 0; k0 < K; k0 += 16) {
        {
            int gr = m0 + aRow;
            float4 v0 = make_float4(0.f, 0.f, 0.f, 0.f), v1 = v0;
            if (gr < M) {
                const float* pa = A + (size_t)gr * K + k0 + aK;
                v0 = *(const float4*)pa;
                v1 = *(const float4*)(pa + 4);
            }
            uint32_t* ps = &As[aRow][aK];
            ps[0] = f2tf(v0.x); ps[1] = f2tf(v0.y); ps[2] = f2tf(v0.z); ps[3] = f2tf(v0.w);
            ps[4] = f2tf(v1.x); ps[5] = f2tf(v1.y); ps[6] = f2tf(v1.z); ps[7] = f2tf(v1.w);
        }
        {
            const float* pb = B + (size_t)(k0 + bRow) * Nc + n0 + bCol;
            float4 v0 = *(const float4*)pb;
            float4 v1 = *(const float4*)(pb + 4);
            uint32_t* ps = &Bs[bRow][bCol];
            ps[0] = f2tf(v0.x); ps[1] = f2tf(v0.y); ps[2] = f2tf(v0.z); ps[3] = f2tf(v0.w);
            ps[4] = f2tf(v1.x); ps[5] = f2tf(v1.y); ps[6] = f2tf(v1.z); ps[7] = f2tf(v1.w);
        }
        __syncthreads();

        #pragma unroll
        for (int ks = 0; ks < 16; ks += 8) {
            uint32_t a[4][4];
            #pragma unroll
            for (int i = 0; i < 4; i++) {
                int m = warp_m + i * 16;
                a[i][0] = As[m + g    ][ks + t4];
                a[i][1] = As[m + g + 8][ks + t4];
                a[i][2] = As[m + g    ][ks + t4 + 4];
                a[i][3] = As[m + g + 8][ks + t4 + 4];
            }
            uint32_t b[4][2];
            #pragma unroll
            for (int j = 0; j < 4; j++) {
                int n = warp_n + j * 8;
                b[j][0] = Bs[ks + t4    ][n + g];
                b[j][1] = Bs[ks + t4 + 4][n + g];
            }
            #pragma unroll
            for (int i = 0; i < 4; i++)
                #pragma unroll
                for (int j = 0; j < 4; j++) {
                    float* cc = c[i * 4 + j];
                    asm volatile(
                        "mma.sync.aligned.m16n8k8.row.col.f32.tf32.tf32.f32 "
                        "{%0,%1,%2,%3}, {%4,%5,%6,%7}, {%8,%9}, {%0,%1,%2,%3};"
                        : "+f"(cc[0]), "+f"(cc[1]), "+f"(cc[2]), "+f"(cc[3])
                        : "r"(a[i][0]), "r"(a[i][1]), "r"(a[i][2]), "r"(a[i][3]),
                          "r"(b[j][0]), "r"(b[j][1]));
                }
        }
        __syncthreads();
    }

    #pragma unroll
    for (int i = 0; i < 4; i++) {
        #pragma unroll
        for (int j = 0; j < 4; j++) {
            float* cc = c[i * 4 + j];
            int col = n0 + warp_n + j * 8 + t4 * 2;
            float b0 = bias[col], b1 = bias[col + 1];
            int r0 = m0 + warp_m + i * 16 + g;
            if (r0 < M) {
                float2* p = (float2*)(C + (size_t)r0 * Nc + col);
                *p = make_float2(cc[0] + b0, cc[1] + b1);
            }
            int r1 = r0 + 8;
            if (r1 < M) {
                float2* p = (float2*)(C + (size_t)r1 * Nc + col);
                *p = make_float2(cc[2] + b0, cc[3] + b1);
            }
        }
    }
}

// ---------------- CSR build ----------------
__global__ void csr_zero_kernel(int* __restrict__ deg, int* __restrict__ cur)
{
    int i = blockIdx.x * blockDim.x + threadIdx.x;
    if (i < N_NODES) { deg[i] = 0; cur[i] = 0; }
}

__global__ void csr_count_kernel(const int* __restrict__ ei, int* __restrict__ deg)
{
    int i = blockIdx.x * blockDim.x + threadIdx.x;
    if (i >= EPRIME) return;
    int d = (i < NE) ? ei[NE + i] : i - NE;
    atomicAdd(&deg[d], 1);
}

// single block, 1024 threads, two-level exclusive scan of deg -> off
__global__ __launch_bounds__(1024) void csr_scan_kernel(const int* __restrict__ deg,
                                                        int* __restrict__ off)
{
    __shared__ int part[1024];
    const int CHUNK = (N_NODES + 1023) / 1024;   // 49
    int t = threadIdx.x;
    int base = t * CHUNK;
    int s = 0;
    for (int j = 0; j < CHUNK; j++) {
        int idx = base + j;
        if (idx < N_NODES) s += deg[idx];
    }
    part[t] = s;
    __syncthreads();
    // Hillis-Steele inclusive scan
    for (int o = 1; o < 1024; o <<= 1) {
        int v = (t >= o) ? part[t - o] : 0;
        __syncthreads();
        part[t] += v;
        __syncthreads();
    }
    int prefix = (t > 0) ? part[t - 1] : 0;
    for (int j = 0; j < CHUNK; j++) {
        int idx = base + j;
        if (idx < N_NODES) {
            off[idx] = prefix;
            prefix += deg[idx];
        }
    }
    if (t == 1023) off[N_NODES] = part[1023];
}

__global__ void csr_fill_kernel(const int* __restrict__ ei, const int* __restrict__ off,
                                int* __restrict__ cur, int2* __restrict__ csr)
{
    int i = blockIdx.x * blockDim.x + threadIdx.x;
    if (i >= EPRIME) return;
    int s, d;
    if (i < NE) { s = ei[i]; d = ei[NE + i]; } else { s = i - NE; d = s; }
    int pos = off[d] + atomicAdd(&cur[d], 1);
    csr[pos] = make_int2(s, i);
}

// ---------------- fused per-node GATv2 layer (warp per node, online softmax) --------
// out = elu( sum_e alpha_e * xl[src_e] + bias + h_in );  also stores raw logits, m, denom.
// if clf_W != nullptr, also computes preds[node] = out . clf_W + clf_b.
__global__ __launch_bounds__(256) void node_layer_kernel(
    const float* __restrict__ xl, const float* __restrict__ xr,
    const float* __restrict__ h_in, const float* __restrict__ att,
    const float* __restrict__ bias,
    const int* __restrict__ off, const int2* __restrict__ csr,
    float* __restrict__ logits, float* __restrict__ mstat, float* __restrict__ dstat,
    float* __restrict__ h_out,
    const float* __restrict__ clf_W, const float* __restrict__ clf_b,
    float* __restrict__ preds)
{
    int w = (blockIdx.x * 256 + threadIdx.x) >> 5;
    int lane = threadIdx.x & 31;
    if (w >= N_NODES) return;
    int h = lane >> 3;

    // per-lane slice: features [lane*8, lane*8+8)
    float xrv[8], attv[8];
    {
        const float4* p = (const float4*)(xr + (size_t)w * HID + lane * 8);
        float4 a = p[0], b = p[1];
        xrv[0]=a.x; xrv[1]=a.y; xrv[2]=a.z; xrv[3]=a.w;
        xrv[4]=b.x; xrv[5]=b.y; xrv[6]=b.z; xrv[7]=b.w;
        const float4* q = (const float4*)(att + lane * 8);
        float4 c = q[0], d = q[1];
        attv[0]=c.x; attv[1]=c.y; attv[2]=c.z; attv[3]=c.w;
        attv[4]=d.x; attv[5]=d.y; attv[6]=d.z; attv[7]=d.w;
    }

    float acc[8];
    #pragma unroll
    for (int q = 0; q < 8; q++) acc[q] = 0.f;
    float mval = -INFINITY, dnm = 0.f;

    int start = off[w], end = off[w + 1];
    for (int i = start; i < end; i++) {
        int2 se = csr[i];
        float xlv[8];
        {
            const float4* p = (const float4*)(xl + (size_t)se.x * HID + lane * 8);
            float4 a = p[0], b = p[1];
            xlv[0]=a.x; xlv[1]=a.y; xlv[2]=a.z; xlv[3]=a.w;
            xlv[4]=b.x; xlv[5]=b.y; xlv[6]=b.z; xlv[7]=b.w;
        }
        float part = 0.f;
        #pragma unroll
        for (int q = 0; q < 8; q++) {
            float v = xlv[q] + xrv[q];
            v = v > 0.f ? v : 0.2f * v;
            part += v * attv[q];
        }
        part += __shfl_xor_sync(0xffffffffu, part, 1);
        part += __shfl_xor_sync(0xffffffffu, part, 2);
        part += __shfl_xor_sync(0xffffffffu, part, 4);
        float logit = part;                          // all 8 lanes of group hold it
        if ((lane & 7) == 0) logits[(size_t)se.y * 4 + h] = logit;

        float mnew = fmaxf(mval, logit);
        float scale = __expf(mval - mnew);           // 0 on first edge (exp(-inf))
        float p = __expf(logit - mnew);
        dnm = dnm * scale + p;
        #pragma unroll
        for (int q = 0; q < 8; q++) acc[q] = acc[q] * scale + p * xlv[q];
        mval = mnew;
    }

    if ((lane & 7) == 0) {
        mstat[(size_t)w * 4 + h] = mval;
        dstat[(size_t)w * 4 + h] = dnm;
    }

    float inv = 1.f / (dnm + 1e-16f);
    float hv[8];
    {
        const float4* pb = (const float4*)(bias + lane * 8);
        float4 b0 = pb[0], b1 = pb[1];
        const float4* ph = (const float4*)(h_in + (size_t)w * HID + lane * 8);
        float4 r0 = ph[0], r1 = ph[1];
        float bb[8] = {b0.x,b0.y,b0.z,b0.w,b1.x,b1.y,b1.z,b1.w};
        float rr[8] = {r0.x,r0.y,r0.z,r0.w,r1.x,r1.y,r1.z,r1.w};
        #pragma unroll
        for (int q = 0; q < 8; q++) {
            float v = acc[q] * inv + bb[q] + rr[q];
            hv[q] = v > 0.f ? v : expm1f(v);
        }
    }
    {
        float4* po = (float4*)(h_out + (size_t)w * HID + lane * 8);
        po[0] = make_float4(hv[0], hv[1], hv[2], hv[3]);
        po[1] = make_float4(hv[4], hv[5], hv[6], hv[7]);
    }

    if (clf_W != nullptr) {
        const float4* pw = (const float4*)(clf_W + lane * 8);
        float4 w0 = pw[0], w1 = pw[1];
        float ww[8] = {w0.x,w0.y,w0.z,w0.w,w1.x,w1.y,w1.z,w1.w};
        float cacc = 0.f;
        #pragma unroll
        for (int q = 0; q < 8; q++) cacc += hv[q] * ww[q];
        #pragma unroll
        for (int o = 16; o; o >>= 1) cacc += __shfl_xor_sync(0xffffffffu, cacc, o);
        if (lane == 0) preds[w] = cacc + clf_b[0];
    }
}

// ---------------- alpha in original edge order ----------------
__global__ void alpha_kernel(const int* __restrict__ ei, const float* __restrict__ logits,
                             const float* __restrict__ mstat, const float* __restrict__ dstat,
                             float* __restrict__ alpha)
{
    long long i = (long long)blockIdx.x * blockDim.x + threadIdx.x;
    if (i >= (long long)EPRIME * 4) return;
    int e = (int)(i >> 2), h = (int)(i & 3);
    int d = (e < NE) ? ei[NE + e] : e - NE;
    float m = mstat[(size_t)d * 4 + h];
    float dn = dstat[(size_t)d * 4 + h];
    alpha[i] = __expf(logits[i] - m) / (dn + 1e-16f);
}

// ---------------- host orchestration ----------------
extern "C" void kernel_launch(void* const* d_in, const int* in_sizes, int n_in,
                              void* d_out, int out_size)
{
    const float* x     = (const float*)d_in[0];
    const int*   ei    = (const int*)d_in[1];
    const float* enc_W = (const float*)d_in[2];
    const float* enc_b = (const float*)d_in[3];
    const float* Wl0   = (const float*)d_in[4];
    const float* bl0   = (const float*)d_in[5];
    const float* Wr0   = (const float*)d_in[6];
    const float* br0   = (const float*)d_in[7];
    const float* att0  = (const float*)d_in[8];
    const float* bias0 = (const float*)d_in[9];
    const float* Wl1   = (const float*)d_in[10];
    const float* bl1   = (const float*)d_in[11];
    const float* Wr1   = (const float*)d_in[12];
    const float* br1   = (const float*)d_in[13];
    const float* att1  = (const float*)d_in[14];
    const float* bias1 = (const float*)d_in[15];
    const float* clf_W = (const float*)d_in[16];
    const float* clf_b = (const float*)d_in[17];

    float* out    = (float*)d_out;
    float* preds  = out;
    float* alpha0 = out + N_NODES;
    float* alpha1 = alpha0 + (size_t)EPRIME * 4;

    float *h0, *h1, *h2, *xl, *xr, *logits, *mstat, *dstat;
    int *deg, *cur, *off; int2* csr;
    cudaGetSymbolAddress((void**)&h0, g_h0);
    cudaGetSymbolAddress((void**)&h1, g_h1);
    cudaGetSymbolAddress((void**)&h2, g_h2);
    cudaGetSymbolAddress((void**)&xl, g_xl);
    cudaGetSymbolAddress((void**)&xr, g_xr);
    cudaGetSymbolAddress((void**)&logits, g_logits);
    cudaGetSymbolAddress((void**)&mstat, g_mstat);
    cudaGetSymbolAddress((void**)&dstat, g_dstat);
    cudaGetSymbolAddress((void**)&deg, g_deg);
    cudaGetSymbolAddress((void**)&cur, g_cur);
    cudaGetSymbolAddress((void**)&off, g_off);
    cudaGetSymbolAddress((void**)&csr, g_csr);

    dim3 gemmGrid(HID / 128, (N_NODES + 127) / 128);
    int nodeWarpBlocks = (N_NODES * 32 + 255) / 256;
    int edgeBlocks = (EPRIME + 255) / 256;
    int edgeHeadBlocks = (EPRIME * 4 + 255) / 256;

    // CSR build (shared by both layers) — overlaps conceptually with encoder GEMM
    csr_zero_kernel<<<(N_NODES + 255) / 256, 256>>>(deg, cur);
    csr_count_kernel<<<edgeBlocks, 256>>>(ei, deg);
    csr_scan_kernel<<<1, 1024>>>(deg, off);
    csr_fill_kernel<<<edgeBlocks, 256>>>(ei, off, cur, csr);

    // encoder
    gemm_tf32_bias<<<gemmGrid, 256>>>(x, enc_W, enc_b, h0, N_NODES, IN_DIM, HID);

    // ----- layer 0 -----
    gemm_tf32_bias<<<gemmGrid, 256>>>(h0, Wl0, bl0, xl, N_NODES, HID, HID);
    gemm_tf32_bias<<<gemmGrid, 256>>>(h0, Wr0, br0, xr, N_NODES, HID, HID);
    node_layer_kernel<<<nodeWarpBlocks, 256>>>(xl, xr, h0, att0, bias0, off, csr,
                                               logits, mstat, dstat, h1,
                                               nullptr, nullptr, nullptr);
    alpha_kernel<<<edgeHeadBlocks, 256>>>(ei, logits, mstat, dstat, alpha0);

    // ----- layer 1 -----
    gemm_tf32_bias<<<gemmGrid, 256>>>(h1, Wl1, bl1, xl, N_NODES, HID, HID);
    gemm_tf32_bias<<<gemmGrid, 256>>>(h1, Wr1, br1, xr, N_NODES, HID, HID);
    node_layer_kernel<<<nodeWarpBlocks, 256>>>(xl, xr, h1, att1, bias1, off, csr,
                                               logits, mstat, dstat, h2,
                                               clf_W, clf_b, preds);
    alpha_kernel<<<edgeHeadBlocks, 256>>>(ei, logits, mstat, dstat, alpha1);
}

// round 4
// speedup vs baseline: 3.0374x; 1.1798x over previous
#include <cuda_runtime.h>
#include <cuda_bf16.h>
#include <math.h>
#include <stdint.h>

#define N_NODES 50000
#define NE      800000
#define EPRIME  850000            // NE + N_NODES (self loops appended)
#define HID     256               // = H*D
#define IN_DIM  1280

// ---------------- device scratch (no allocs allowed) ----------------
__device__ float    g_h0[N_NODES * HID];
__device__ float    g_h1[N_NODES * HID];
__device__ float    g_h2[N_NODES * HID];
__device__ float    g_xl[N_NODES * HID];
__device__ float    g_xr[N_NODES * HID];
__device__ float    g_logits[(size_t)EPRIME * 4];
__device__ float    g_mstat[N_NODES * 4];
__device__ float    g_dstat[N_NODES * 4];
__device__ int      g_deg[N_NODES];
__device__ int      g_cur[N_NODES];
__device__ int      g_off[N_NODES + 1];
__device__ int2     g_csr[EPRIME];          // .x = src node, .y = original edge id

__device__ __forceinline__ uint32_t f2tf(float x) {
    uint32_t u;
    asm("cvt.rna.tf32.f32 %0, %1;" : "=r"(u) : "f"(x));
    return u;
}

// ---------------- TF32 tensor-core GEMM with cp.async 2-stage pipeline ----------------
// C = A[M,K] @ B[K,Nc] + bias.  BM=BN=128, BK=16, 256 threads, warp tile 64x32.
// fp32 staged raw via cp.async; cvt.rna.tf32 applied after LDS (round-to-nearest kept).
__global__ __launch_bounds__(256, 2) void gemm_tf32_bias(
    const float* __restrict__ A, const float* __restrict__ B,
    const float* __restrict__ bias, float* __restrict__ C,
    int M, int K, int Nc)
{
    __shared__ float As[2][128][20];
    __shared__ float Bs[2][16][136];

    int tid = threadIdx.x;
    int wid = tid >> 5, lane = tid & 31;
    int warp_m = (wid & 1) * 64;
    int warp_n = (wid >> 1) * 32;
    int g = lane >> 2;
    int t4 = lane & 3;

    int m0 = blockIdx.y * 128, n0 = blockIdx.x * 128;

    float c[16][4];
    #pragma unroll
    for (int i = 0; i < 16; i++)
        #pragma unroll
        for (int j = 0; j < 4; j++) c[i][j] = 0.f;

    int aRow = tid >> 1;
    int aK   = (tid & 1) * 8;
    int bRow = tid >> 4;
    int bCol = (tid & 15) * 8;

    int gr = m0 + aRow;
    int aValid = (gr < M) ? 16 : 0;
    const float* paBase = A + (size_t)(gr < M ? gr : 0) * K + aK;
    const float* pbBase = B + (size_t)bRow * Nc + n0 + bCol;

    int nt = K >> 4;

    // issue stage loads for k-tile t into buffer st
    auto issue = [&](int st, int t) {
        const float* pa = paBase + t * 16;
        uint32_t sa = (uint32_t)__cvta_generic_to_shared(&As[st][aRow][aK]);
        asm volatile(
            "cp.async.ca.shared.global [%0], [%1], 16, %2;\n\t"
            "cp.async.ca.shared.global [%3], [%4], 16, %5;"
            :: "r"(sa), "l"(pa), "r"(aValid),
               "r"(sa + 16), "l"(pa + 4), "r"(aValid));
        const float* pb = pbBase + (size_t)t * 16 * Nc;
        uint32_t sb = (uint32_t)__cvta_generic_to_shared(&Bs[st][bRow][bCol]);
        asm volatile(
            "cp.async.ca.shared.global [%0], [%1], 16;\n\t"
            "cp.async.ca.shared.global [%2], [%3], 16;"
            :: "r"(sb), "l"(pb), "r"(sb + 16), "l"(pb + 4));
    };

    issue(0, 0);
    asm volatile("cp.async.commit_group;");

    for (int t = 0; t < nt; t++) {
        if (t + 1 < nt) issue((t + 1) & 1, t + 1);
        asm volatile("cp.async.commit_group;");
        asm volatile("cp.async.wait_group 1;");
        __syncthreads();

        int st = t & 1;
        #pragma unroll
        for (int ks = 0; ks < 16; ks += 8) {
            uint32_t a[4][4];
            #pragma unroll
            for (int i = 0; i < 4; i++) {
                int m = warp_m + i * 16;
                a[i][0] = f2tf(As[st][m + g    ][ks + t4]);
                a[i][1] = f2tf(As[st][m + g + 8][ks + t4]);
                a[i][2] = f2tf(As[st][m + g    ][ks + t4 + 4]);
                a[i][3] = f2tf(As[st][m + g + 8][ks + t4 + 4]);
            }
            uint32_t b[4][2];
            #pragma unroll
            for (int j = 0; j < 4; j++) {
                int n = warp_n + j * 8;
                b[j][0] = f2tf(Bs[st][ks + t4    ][n + g]);
                b[j][1] = f2tf(Bs[st][ks + t4 + 4][n + g]);
            }
            #pragma unroll
            for (int i = 0; i < 4; i++)
                #pragma unroll
                for (int j = 0; j < 4; j++) {
                    float* cc = c[i * 4 + j];
                    asm volatile(
                        "mma.sync.aligned.m16n8k8.row.col.f32.tf32.tf32.f32 "
                        "{%0,%1,%2,%3}, {%4,%5,%6,%7}, {%8,%9}, {%0,%1,%2,%3};"
                        : "+f"(cc[0]), "+f"(cc[1]), "+f"(cc[2]), "+f"(cc[3])
                        : "r"(a[i][0]), "r"(a[i][1]), "r"(a[i][2]), "r"(a[i][3]),
                          "r"(b[j][0]), "r"(b[j][1]));
                }
        }
        __syncthreads();
    }

    #pragma unroll
    for (int i = 0; i < 4; i++) {
        #pragma unroll
        for (int j = 0; j < 4; j++) {
            float* cc = c[i * 4 + j];
            int col = n0 + warp_n + j * 8 + t4 * 2;
            float b0 = bias[col], b1 = bias[col + 1];
            int r0 = m0 + warp_m + i * 16 + g;
            if (r0 < M) {
                float2* p = (float2*)(C + (size_t)r0 * Nc + col);
                *p = make_float2(cc[0] + b0, cc[1] + b1);
            }
            int r1 = r0 + 8;
            if (r1 < M) {
                float2* p = (float2*)(C + (size_t)r1 * Nc + col);
                *p = make_float2(cc[2] + b0, cc[3] + b1);
            }
        }
    }
}

// ---------------- CSR build ----------------
__global__ void csr_zero_kernel(int* __restrict__ deg, int* __restrict__ cur)
{
    int i = blockIdx.x * blockDim.x + threadIdx.x;
    if (i < N_NODES) { deg[i] = 0; cur[i] = 0; }
}

__global__ void csr_count_kernel(const int* __restrict__ ei, int* __restrict__ deg)
{
    int i = blockIdx.x * blockDim.x + threadIdx.x;
    if (i >= EPRIME) return;
    int d = (i < NE) ? ei[NE + i] : i - NE;
    atomicAdd(&deg[d], 1);
}

__global__ __launch_bounds__(1024) void csr_scan_kernel(const int* __restrict__ deg,
                                                        int* __restrict__ off)
{
    __shared__ int part[1024];
    const int CHUNK = (N_NODES + 1023) / 1024;
    int t = threadIdx.x;
    int base = t * CHUNK;
    int s = 0;
    for (int j = 0; j < CHUNK; j++) {
        int idx = base + j;
        if (idx < N_NODES) s += deg[idx];
    }
    part[t] = s;
    __syncthreads();
    for (int o = 1; o < 1024; o <<= 1) {
        int v = (t >= o) ? part[t - o] : 0;
        __syncthreads();
        part[t] += v;
        __syncthreads();
    }
    int prefix = (t > 0) ? part[t - 1] : 0;
    for (int j = 0; j < CHUNK; j++) {
        int idx = base + j;
        if (idx < N_NODES) {
            off[idx] = prefix;
            prefix += deg[idx];
        }
    }
    if (t == 1023) off[N_NODES] = part[1023];
}

__global__ void csr_fill_kernel(const int* __restrict__ ei, const int* __restrict__ off,
                                int* __restrict__ cur, int2* __restrict__ csr)
{
    int i = blockIdx.x * blockDim.x + threadIdx.x;
    if (i >= EPRIME) return;
    int s, d;
    if (i < NE) { s = ei[i]; d = ei[NE + i]; } else { s = i - NE; d = s; }
    int pos = off[d] + atomicAdd(&cur[d], 1);
    csr[pos] = make_int2(s, i);
}

// ---------------- fused per-node GATv2 layer (warp per node, online softmax) --------
// Software-pipelined: next edge's csr entry + xl row prefetched while computing current.
__global__ __launch_bounds__(256) void node_layer_kernel(
    const float* __restrict__ xl, const float* __restrict__ xr,
    const float* __restrict__ h_in, const float* __restrict__ att,
    const float* __restrict__ bias,
    const int* __restrict__ off, const int2* __restrict__ csr,
    float* __restrict__ logits, float* __restrict__ mstat, float* __restrict__ dstat,
    float* __restrict__ h_out,
    const float* __restrict__ clf_W, const float* __restrict__ clf_b,
    float* __restrict__ preds)
{
    int w = (blockIdx.x * 256 + threadIdx.x) >> 5;
    int lane = threadIdx.x & 31;
    if (w >= N_NODES) return;
    int h = lane >> 3;

    float xrv[8], attv[8];
    {
        const float4* p = (const float4*)(xr + (size_t)w * HID + lane * 8);
        float4 a = p[0], b = p[1];
        xrv[0]=a.x; xrv[1]=a.y; xrv[2]=a.z; xrv[3]=a.w;
        xrv[4]=b.x; xrv[5]=b.y; xrv[6]=b.z; xrv[7]=b.w;
        const float4* q = (const float4*)(att + lane * 8);
        float4 c = q[0], d = q[1];
        attv[0]=c.x; attv[1]=c.y; attv[2]=c.z; attv[3]=c.w;
        attv[4]=d.x; attv[5]=d.y; attv[6]=d.z; attv[7]=d.w;
    }

    float acc[8];
    #pragma unroll
    for (int q = 0; q < 8; q++) acc[q] = 0.f;
    float mval = -INFINITY, dnm = 0.f;

    int start = off[w], end = off[w + 1];

    int2 se = make_int2(0, 0);
    float4 xa0 = make_float4(0,0,0,0), xa1 = xa0;
    if (start < end) {
        se = csr[start];
        const float4* p = (const float4*)(xl + (size_t)se.x * HID + lane * 8);
        xa0 = p[0]; xa1 = p[1];
    }

    for (int i = start; i < end; i++) {
        // prefetch next edge
        int2 se_n = se;
        float4 xn0 = xa0, xn1 = xa1;
        if (i + 1 < end) {
            se_n = csr[i + 1];
            const float4* p = (const float4*)(xl + (size_t)se_n.x * HID + lane * 8);
            xn0 = p[0]; xn1 = p[1];
        }

        float xlv[8] = {xa0.x, xa0.y, xa0.z, xa0.w, xa1.x, xa1.y, xa1.z, xa1.w};
        float part = 0.f;
        #pragma unroll
        for (int q = 0; q < 8; q++) {
            float v = xlv[q] + xrv[q];
            v = v > 0.f ? v : 0.2f * v;
            part += v * attv[q];
        }
        part += __shfl_xor_sync(0xffffffffu, part, 1);
        part += __shfl_xor_sync(0xffffffffu, part, 2);
        part += __shfl_xor_sync(0xffffffffu, part, 4);
        float logit = part;
        if ((lane & 7) == 0) logits[(size_t)se.y * 4 + h] = logit;

        float mnew = fmaxf(mval, logit);
        float scale = __expf(mval - mnew);
        float p = __expf(logit - mnew);
        dnm = dnm * scale + p;
        #pragma unroll
        for (int q = 0; q < 8; q++) acc[q] = acc[q] * scale + p * xlv[q];
        mval = mnew;

        se = se_n; xa0 = xn0; xa1 = xn1;
    }

    if ((lane & 7) == 0) {
        mstat[(size_t)w * 4 + h] = mval;
        dstat[(size_t)w * 4 + h] = dnm;
    }

    float inv = 1.f / (dnm + 1e-16f);
    float hv[8];
    {
        const float4* pb = (const float4*)(bias + lane * 8);
        float4 b0 = pb[0], b1 = pb[1];
        const float4* ph = (const float4*)(h_in + (size_t)w * HID + lane * 8);
        float4 r0 = ph[0], r1 = ph[1];
        float bb[8] = {b0.x,b0.y,b0.z,b0.w,b1.x,b1.y,b1.z,b1.w};
        float rr[8] = {r0.x,r0.y,r0.z,r0.w,r1.x,r1.y,r1.z,r1.w};
        #pragma unroll
        for (int q = 0; q < 8; q++) {
            float v = acc[q] * inv + bb[q] + rr[q];
            hv[q] = v > 0.f ? v : expm1f(v);
        }
    }
    {
        float4* po = (float4*)(h_out + (size_t)w * HID + lane * 8);
        po[0] = make_float4(hv[0], hv[1], hv[2], hv[3]);
        po[1] = make_float4(hv[4], hv[5], hv[6], hv[7]);
    }

    if (clf_W != nullptr) {
        const float4* pw = (const float4*)(clf_W + lane * 8);
        float4 w0 = pw[0], w1 = pw[1];
        float ww[8] = {w0.x,w0.y,w0.z,w0.w,w1.x,w1.y,w1.z,w1.w};
        float cacc = 0.f;
        #pragma unroll
        for (int q = 0; q < 8; q++) cacc += hv[q] * ww[q];
        #pragma unroll
        for (int o = 16; o; o >>= 1) cacc += __shfl_xor_sync(0xffffffffu, cacc, o);
        if (lane == 0) preds[w] = cacc + clf_b[0];
    }
}

// ---------------- alpha in original edge order ----------------
__global__ void alpha_kernel(const int* __restrict__ ei, const float* __restrict__ logits,
                             const float* __restrict__ mstat, const float* __restrict__ dstat,
                             float* __restrict__ alpha)
{
    long long i = (long long)blockIdx.x * blockDim.x + threadIdx.x;
    if (i >= (long long)EPRIME * 4) return;
    int e = (int)(i >> 2), h = (int)(i & 3);
    int d = (e < NE) ? ei[NE + e] : e - NE;
    float m = mstat[(size_t)d * 4 + h];
    float dn = dstat[(size_t)d * 4 + h];
    alpha[i] = __expf(logits[i] - m) / (dn + 1e-16f);
}

// ---------------- host orchestration ----------------
extern "C" void kernel_launch(void* const* d_in, const int* in_sizes, int n_in,
                              void* d_out, int out_size)
{
    const float* x     = (const float*)d_in[0];
    const int*   ei    = (const int*)d_in[1];
    const float* enc_W = (const float*)d_in[2];
    const float* enc_b = (const float*)d_in[3];
    const float* Wl0   = (const float*)d_in[4];
    const float* bl0   = (const float*)d_in[5];
    const float* Wr0   = (const float*)d_in[6];
    const float* br0   = (const float*)d_in[7];
    const float* att0  = (const float*)d_in[8];
    const float* bias0 = (const float*)d_in[9];
    const float* Wl1   = (const float*)d_in[10];
    const float* bl1   = (const float*)d_in[11];
    const float* Wr1   = (const float*)d_in[12];
    const float* br1   = (const float*)d_in[13];
    const float* att1  = (const float*)d_in[14];
    const float* bias1 = (const float*)d_in[15];
    const float* clf_W = (const float*)d_in[16];
    const float* clf_b = (const float*)d_in[17];

    float* out    = (float*)d_out;
    float* preds  = out;
    float* alpha0 = out + N_NODES;
    float* alpha1 = alpha0 + (size_t)EPRIME * 4;

    float *h0, *h1, *h2, *xl, *xr, *logits, *mstat, *dstat;
    int *deg, *cur, *off; int2* csr;
    cudaGetSymbolAddress((void**)&h0, g_h0);
    cudaGetSymbolAddress((void**)&h1, g_h1);
    cudaGetSymbolAddress((void**)&h2, g_h2);
    cudaGetSymbolAddress((void**)&xl, g_xl);
    cudaGetSymbolAddress((void**)&xr, g_xr);
    cudaGetSymbolAddress((void**)&logits, g_logits);
    cudaGetSymbolAddress((void**)&mstat, g_mstat);
    cudaGetSymbolAddress((void**)&dstat, g_dstat);
    cudaGetSymbolAddress((void**)&deg, g_deg);
    cudaGetSymbolAddress((void**)&cur, g_cur);
    cudaGetSymbolAddress((void**)&off, g_off);
    cudaGetSymbolAddress((void**)&csr, g_csr);

    dim3 gemmGrid(HID / 128, (N_NODES + 127) / 128);
    int nodeWarpBlocks = (N_NODES * 32 + 255) / 256;
    int edgeBlocks = (EPRIME + 255) / 256;
    int edgeHeadBlocks = (EPRIME * 4 + 255) / 256;

    // CSR build (shared by both layers)
    csr_zero_kernel<<<(N_NODES + 255) / 256, 256>>>(deg, cur);
    csr_count_kernel<<<edgeBlocks, 256>>>(ei, deg);
    csr_scan_kernel<<<1, 1024>>>(deg, off);
    csr_fill_kernel<<<edgeBlocks, 256>>>(ei, off, cur, csr);

    // encoder
    gemm_tf32_bias<<<gemmGrid, 256>>>(x, enc_W, enc_b, h0, N_NODES, IN_DIM, HID);

    // ----- layer 0 -----
    gemm_tf32_bias<<<gemmGrid, 256>>>(h0, Wl0, bl0, xl, N_NODES, HID, HID);
    gemm_tf32_bias<<<gemmGrid, 256>>>(h0, Wr0, br0, xr, N_NODES, HID, HID);
    node_layer_kernel<<<nodeWarpBlocks, 256>>>(xl, xr, h0, att0, bias0, off, csr,
                                               logits, mstat, dstat, h1,
                                               nullptr, nullptr, nullptr);
    alpha_kernel<<<edgeHeadBlocks, 256>>>(ei, logits, mstat, dstat, alpha0);

    // ----- layer 1 -----
    gemm_tf32_bias<<<gemmGrid, 256>>>(h1, Wl1, bl1, xl, N_NODES, HID, HID);
    gemm_tf32_bias<<<gemmGrid, 256>>>(h1, Wr1, br1, xr, N_NODES, HID, HID);
    node_layer_kernel<<<nodeWarpBlocks, 256>>>(xl, xr, h1, att1, bias1, off, csr,
                                               logits, mstat, dstat, h2,
                                               clf_W, clf_b, preds);
    alpha_kernel<<<edgeHeadBlocks, 256>>>(ei, logits, mstat, dstat, alpha1);
}

// round 5
// speedup vs baseline: 3.0797x; 1.0139x over previous
#include <cuda_runtime.h>
#include <cuda_bf16.h>
#include <math.h>
#include <stdint.h>

#define N_NODES 50000
#define NE      800000
#define EPRIME  850000            // NE + N_NODES (self loops appended)
#define HID     256               // = H*D
#define IN_DIM  1280

// ---------------- device scratch (no allocs allowed) ----------------
__device__ float    g_h0[N_NODES * HID];
__device__ float    g_h1[N_NODES * HID];
__device__ float    g_h2[N_NODES * HID];
__device__ float    g_xlr[(size_t)N_NODES * 512];   // [xl | xr] per node
__device__ float    g_wcat[2][HID * 512];
__device__ float    g_bcat[2][512];
__device__ float    g_logits[(size_t)EPRIME * 4];
__device__ float    g_mstat[N_NODES * 4];
__device__ float    g_dstat[N_NODES * 4];
__device__ int      g_deg[N_NODES];
__device__ int      g_cur[N_NODES];
__device__ int      g_off[N_NODES + 1];
__device__ int2     g_csr[EPRIME];          // .x = src node, .y = original edge id

__device__ __forceinline__ uint32_t f2tf(float x) {
    uint32_t u;
    asm("cvt.rna.tf32.f32 %0, %1;" : "=r"(u) : "f"(x));
    return u;
}

// ---------------- weight concat: Wcat = [Wl | Wr], bcat = [bl | br] ----------------
__global__ void concat_w_kernel(const float* __restrict__ Wl, const float* __restrict__ Wr,
                                const float* __restrict__ bl, const float* __restrict__ br,
                                float* __restrict__ Wcat, float* __restrict__ bcat)
{
    int i = blockIdx.x * blockDim.x + threadIdx.x;
    if (i < HID * 512) {
        int row = i >> 9, col = i & 511;
        Wcat[i] = (col < 256) ? Wl[row * 256 + col] : Wr[row * 256 + col - 256];
    }
    if (i < 512) bcat[i] = (i < 256) ? bl[i] : br[i - 256];
}

// ---------------- TF32 tensor-core GEMM, 3-stage cp.async pipeline ----------------
// C = A[M,K] @ B[K,Nc] + bias.  BM=BN=128, BK=16, 256 threads, warp tile 64x32.
// Dynamic smem: As 3*128*20 floats, Bs 3*16*136 floats.
#define AS_OFF(st, r, c) (((st) * 128 + (r)) * 20 + (c))
#define BS_OFF(st, r, c) (3 * 128 * 20 + ((st) * 16 + (r)) * 136 + (c))
#define GEMM_SMEM ((3 * 128 * 20 + 3 * 16 * 136) * 4)

__global__ __launch_bounds__(256, 2) void gemm_tf32_bias(
    const float* __restrict__ A, const float* __restrict__ B,
    const float* __restrict__ bias, float* __restrict__ C,
    int M, int K, int Nc)
{
    extern __shared__ float smem[];

    int tid = threadIdx.x;
    int wid = tid >> 5, lane = tid & 31;
    int warp_m = (wid & 1) * 64;
    int warp_n = (wid >> 1) * 32;
    int g = lane >> 2;
    int t4 = lane & 3;

    int m0 = blockIdx.y * 128, n0 = blockIdx.x * 128;

    float c[16][4];
    #pragma unroll
    for (int i = 0; i < 16; i++)
        #pragma unroll
        for (int j = 0; j < 4; j++) c[i][j] = 0.f;

    int aRow = tid >> 1;
    int aK   = (tid & 1) * 8;
    int bRow = tid >> 4;
    int bCol = (tid & 15) * 8;

    int gr = m0 + aRow;
    int aValid = (gr < M) ? 16 : 0;
    const float* paBase = A + (size_t)(gr < M ? gr : 0) * K + aK;
    const float* pbBase = B + (size_t)bRow * Nc + n0 + bCol;

    int nt = K >> 4;

    auto issue = [&](int st, int t) {
        const float* pa = paBase + t * 16;
        uint32_t sa = (uint32_t)__cvta_generic_to_shared(&smem[AS_OFF(st, aRow, aK)]);
        asm volatile(
            "cp.async.ca.shared.global [%0], [%1], 16, %2;\n\t"
            "cp.async.ca.shared.global [%3], [%4], 16, %5;"
            :: "r"(sa), "l"(pa), "r"(aValid),
               "r"(sa + 16), "l"(pa + 4), "r"(aValid));
        const float* pb = pbBase + (size_t)t * 16 * Nc;
        uint32_t sb = (uint32_t)__cvta_generic_to_shared(&smem[BS_OFF(st, bRow, bCol)]);
        asm volatile(
            "cp.async.ca.shared.global [%0], [%1], 16;\n\t"
            "cp.async.ca.shared.global [%2], [%3], 16;"
            :: "r"(sb), "l"(pb), "r"(sb + 16), "l"(pb + 4));
    };

    issue(0, 0);
    asm volatile("cp.async.commit_group;");
    if (nt > 1) {
        issue(1, 1);
        asm volatile("cp.async.commit_group;");
    }

    for (int t = 0; t < nt; t++) {
        if (t + 1 < nt) { asm volatile("cp.async.wait_group 1;"); }
        else            { asm volatile("cp.async.wait_group 0;"); }
        __syncthreads();

        if (t + 2 < nt) {
            issue((t + 2) % 3, t + 2);
            asm volatile("cp.async.commit_group;");
        }

        int st = t % 3;
        #pragma unroll
        for (int ks = 0; ks < 16; ks += 8) {
            uint32_t a[4][4];
            #pragma unroll
            for (int i = 0; i < 4; i++) {
                int m = warp_m + i * 16;
                a[i][0] = f2tf(smem[AS_OFF(st, m + g    , ks + t4)]);
                a[i][1] = f2tf(smem[AS_OFF(st, m + g + 8, ks + t4)]);
                a[i][2] = f2tf(smem[AS_OFF(st, m + g    , ks + t4 + 4)]);
                a[i][3] = f2tf(smem[AS_OFF(st, m + g + 8, ks + t4 + 4)]);
            }
            uint32_t b[4][2];
            #pragma unroll
            for (int j = 0; j < 4; j++) {
                int n = warp_n + j * 8;
                b[j][0] = f2tf(smem[BS_OFF(st, ks + t4    , n + g)]);
                b[j][1] = f2tf(smem[BS_OFF(st, ks + t4 + 4, n + g)]);
            }
            #pragma unroll
            for (int i = 0; i < 4; i++)
                #pragma unroll
                for (int j = 0; j < 4; j++) {
                    float* cc = c[i * 4 + j];
                    asm volatile(
                        "mma.sync.aligned.m16n8k8.row.col.f32.tf32.tf32.f32 "
                        "{%0,%1,%2,%3}, {%4,%5,%6,%7}, {%8,%9}, {%0,%1,%2,%3};"
                        : "+f"(cc[0]), "+f"(cc[1]), "+f"(cc[2]), "+f"(cc[3])
                        : "r"(a[i][0]), "r"(a[i][1]), "r"(a[i][2]), "r"(a[i][3]),
                          "r"(b[j][0]), "r"(b[j][1]));
                }
        }
        __syncthreads();
    }

    #pragma unroll
    for (int i = 0; i < 4; i++) {
        #pragma unroll
        for (int j = 0; j < 4; j++) {
            float* cc = c[i * 4 + j];
            int col = n0 + warp_n + j * 8 + t4 * 2;
            float b0 = bias[col], b1 = bias[col + 1];
            int r0 = m0 + warp_m + i * 16 + g;
            if (r0 < M) {
                float2* p = (float2*)(C + (size_t)r0 * Nc + col);
                *p = make_float2(cc[0] + b0, cc[1] + b1);
            }
            int r1 = r0 + 8;
            if (r1 < M) {
                float2* p = (float2*)(C + (size_t)r1 * Nc + col);
                *p = make_float2(cc[2] + b0, cc[3] + b1);
            }
        }
    }
}

// ---------------- CSR build ----------------
__global__ void csr_zero_kernel(int* __restrict__ deg, int* __restrict__ cur)
{
    int i = blockIdx.x * blockDim.x + threadIdx.x;
    if (i < N_NODES) { deg[i] = 0; cur[i] = 0; }
}

__global__ void csr_count_kernel(const int* __restrict__ ei, int* __restrict__ deg)
{
    int i = blockIdx.x * blockDim.x + threadIdx.x;
    if (i >= EPRIME) return;
    int d = (i < NE) ? ei[NE + i] : i - NE;
    atomicAdd(&deg[d], 1);
}

__global__ __launch_bounds__(1024) void csr_scan_kernel(const int* __restrict__ deg,
                                                        int* __restrict__ off)
{
    __shared__ int part[1024];
    const int CHUNK = (N_NODES + 1023) / 1024;
    int t = threadIdx.x;
    int base = t * CHUNK;
    int s = 0;
    for (int j = 0; j < CHUNK; j++) {
        int idx = base + j;
        if (idx < N_NODES) s += deg[idx];
    }
    part[t] = s;
    __syncthreads();
    for (int o = 1; o < 1024; o <<= 1) {
        int v = (t >= o) ? part[t - o] : 0;
        __syncthreads();
        part[t] += v;
        __syncthreads();
    }
    int prefix = (t > 0) ? part[t - 1] : 0;
    for (int j = 0; j < CHUNK; j++) {
        int idx = base + j;
        if (idx < N_NODES) {
            off[idx] = prefix;
            prefix += deg[idx];
        }
    }
    if (t == 1023) off[N_NODES] = part[1023];
}

__global__ void csr_fill_kernel(const int* __restrict__ ei, const int* __restrict__ off,
                                int* __restrict__ cur, int2* __restrict__ csr)
{
    int i = blockIdx.x * blockDim.x + threadIdx.x;
    if (i >= EPRIME) return;
    int s, d;
    if (i < NE) { s = ei[i]; d = ei[NE + i]; } else { s = i - NE; d = s; }
    int pos = off[d] + atomicAdd(&cur[d], 1);
    csr[pos] = make_int2(s, i);
}

// ---------------- fused per-node GATv2 layer (warp per node, online softmax) --------
// xlr: [N,512] rows = [xl | xr].  Software-pipelined edge loop.
__global__ __launch_bounds__(256) void node_layer_kernel(
    const float* __restrict__ xlr,
    const float* __restrict__ h_in, const float* __restrict__ att,
    const float* __restrict__ bias,
    const int* __restrict__ off, const int2* __restrict__ csr,
    float* __restrict__ logits, float* __restrict__ mstat, float* __restrict__ dstat,
    float* __restrict__ h_out,
    const float* __restrict__ clf_W, const float* __restrict__ clf_b,
    float* __restrict__ preds)
{
    int w = (blockIdx.x * 256 + threadIdx.x) >> 5;
    int lane = threadIdx.x & 31;
    if (w >= N_NODES) return;
    int h = lane >> 3;

    float xrv[8], attv[8];
    {
        const float4* p = (const float4*)(xlr + (size_t)w * 512 + 256 + lane * 8);
        float4 a = p[0], b = p[1];
        xrv[0]=a.x; xrv[1]=a.y; xrv[2]=a.z; xrv[3]=a.w;
        xrv[4]=b.x; xrv[5]=b.y; xrv[6]=b.z; xrv[7]=b.w;
        const float4* q = (const float4*)(att + lane * 8);
        float4 c = q[0], d = q[1];
        attv[0]=c.x; attv[1]=c.y; attv[2]=c.z; attv[3]=c.w;
        attv[4]=d.x; attv[5]=d.y; attv[6]=d.z; attv[7]=d.w;
    }

    float acc[8];
    #pragma unroll
    for (int q = 0; q < 8; q++) acc[q] = 0.f;
    float mval = -INFINITY, dnm = 0.f;

    int start = off[w], end = off[w + 1];

    int2 se = make_int2(0, 0);
    float4 xa0 = make_float4(0,0,0,0), xa1 = xa0;
    if (start < end) {
        se = csr[start];
        const float4* p = (const float4*)(xlr + (size_t)se.x * 512 + lane * 8);
        xa0 = p[0]; xa1 = p[1];
    }

    for (int i = start; i < end; i++) {
        int2 se_n = se;
        float4 xn0 = xa0, xn1 = xa1;
        if (i + 1 < end) {
            se_n = csr[i + 1];
            const float4* p = (const float4*)(xlr + (size_t)se_n.x * 512 + lane * 8);
            xn0 = p[0]; xn1 = p[1];
        }

        float xlv[8] = {xa0.x, xa0.y, xa0.z, xa0.w, xa1.x, xa1.y, xa1.z, xa1.w};
        float part = 0.f;
        #pragma unroll
        for (int q = 0; q < 8; q++) {
            float v = xlv[q] + xrv[q];
            v = v > 0.f ? v : 0.2f * v;
            part += v * attv[q];
        }
        part += __shfl_xor_sync(0xffffffffu, part, 1);
        part += __shfl_xor_sync(0xffffffffu, part, 2);
        part += __shfl_xor_sync(0xffffffffu, part, 4);
        float logit = part;
        if ((lane & 7) == 0) logits[(size_t)se.y * 4 + h] = logit;

        float mnew = fmaxf(mval, logit);
        float scale = __expf(mval - mnew);
        float p = __expf(logit - mnew);
        dnm = dnm * scale + p;
        #pragma unroll
        for (int q = 0; q < 8; q++) acc[q] = acc[q] * scale + p * xlv[q];
        mval = mnew;

        se = se_n; xa0 = xn0; xa1 = xn1;
    }

    if ((lane & 7) == 0) {
        mstat[(size_t)w * 4 + h] = mval;
        dstat[(size_t)w * 4 + h] = dnm;
    }

    float inv = 1.f / (dnm + 1e-16f);
    float hv[8];
    {
        const float4* pb = (const float4*)(bias + lane * 8);
        float4 b0 = pb[0], b1 = pb[1];
        const float4* ph = (const float4*)(h_in + (size_t)w * HID + lane * 8);
        float4 r0 = ph[0], r1 = ph[1];
        float bb[8] = {b0.x,b0.y,b0.z,b0.w,b1.x,b1.y,b1.z,b1.w};
        float rr[8] = {r0.x,r0.y,r0.z,r0.w,r1.x,r1.y,r1.z,r1.w};
        #pragma unroll
        for (int q = 0; q < 8; q++) {
            float v = acc[q] * inv + bb[q] + rr[q];
            hv[q] = v > 0.f ? v : expm1f(v);
        }
    }
    {
        float4* po = (float4*)(h_out + (size_t)w * HID + lane * 8);
        po[0] = make_float4(hv[0], hv[1], hv[2], hv[3]);
        po[1] = make_float4(hv[4], hv[5], hv[6], hv[7]);
    }

    if (clf_W != nullptr) {
        const float4* pw = (const float4*)(clf_W + lane * 8);
        float4 w0 = pw[0], w1 = pw[1];
        float ww[8] = {w0.x,w0.y,w0.z,w0.w,w1.x,w1.y,w1.z,w1.w};
        float cacc = 0.f;
        #pragma unroll
        for (int q = 0; q < 8; q++) cacc += hv[q] * ww[q];
        #pragma unroll
        for (int o = 16; o; o >>= 1) cacc += __shfl_xor_sync(0xffffffffu, cacc, o);
        if (lane == 0) preds[w] = cacc + clf_b[0];
    }
}

// ---------------- alpha in original edge order ----------------
__global__ void alpha_kernel(const int* __restrict__ ei, const float* __restrict__ logits,
                             const float* __restrict__ mstat, const float* __restrict__ dstat,
                             float* __restrict__ alpha)
{
    long long i = (long long)blockIdx.x * blockDim.x + threadIdx.x;
    if (i >= (long long)EPRIME * 4) return;
    int e = (int)(i >> 2), h = (int)(i & 3);
    int d = (e < NE) ? ei[NE + e] : e - NE;
    float m = mstat[(size_t)d * 4 + h];
    float dn = dstat[(size_t)d * 4 + h];
    alpha[i] = __expf(logits[i] - m) / (dn + 1e-16f);
}

// ---------------- host orchestration ----------------
extern "C" void kernel_launch(void* const* d_in, const int* in_sizes, int n_in,
                              void* d_out, int out_size)
{
    const float* x     = (const float*)d_in[0];
    const int*   ei    = (const int*)d_in[1];
    const float* enc_W = (const float*)d_in[2];
    const float* enc_b = (const float*)d_in[3];
    const float* Wl0   = (const float*)d_in[4];
    const float* bl0   = (const float*)d_in[5];
    const float* Wr0   = (const float*)d_in[6];
    const float* br0   = (const float*)d_in[7];
    const float* att0  = (const float*)d_in[8];
    const float* bias0 = (const float*)d_in[9];
    const float* Wl1   = (const float*)d_in[10];
    const float* bl1   = (const float*)d_in[11];
    const float* Wr1   = (const float*)d_in[12];
    const float* br1   = (const float*)d_in[13];
    const float* att1  = (const float*)d_in[14];
    const float* bias1 = (const float*)d_in[15];
    const float* clf_W = (const float*)d_in[16];
    const float* clf_b = (const float*)d_in[17];

    float* out    = (float*)d_out;
    float* preds  = out;
    float* alpha0 = out + N_NODES;
    float* alpha1 = alpha0 + (size_t)EPRIME * 4;

    float *h0, *h1, *h2, *xlr, *logits, *mstat, *dstat, *wcat, *bcat;
    int *deg, *cur, *off; int2* csr;
    cudaGetSymbolAddress((void**)&h0, g_h0);
    cudaGetSymbolAddress((void**)&h1, g_h1);
    cudaGetSymbolAddress((void**)&h2, g_h2);
    cudaGetSymbolAddress((void**)&xlr, g_xlr);
    cudaGetSymbolAddress((void**)&logits, g_logits);
    cudaGetSymbolAddress((void**)&mstat, g_mstat);
    cudaGetSymbolAddress((void**)&dstat, g_dstat);
    cudaGetSymbolAddress((void**)&wcat, g_wcat);
    cudaGetSymbolAddress((void**)&bcat, g_bcat);
    cudaGetSymbolAddress((void**)&deg, g_deg);
    cudaGetSymbolAddress((void**)&cur, g_cur);
    cudaGetSymbolAddress((void**)&off, g_off);
    cudaGetSymbolAddress((void**)&csr, g_csr);

    float* wcat0 = wcat;
    float* wcat1 = wcat + HID * 512;
    float* bcat0 = bcat;
    float* bcat1 = bcat + 512;

    static bool attr_set = false;
    if (!attr_set) {
        cudaFuncSetAttribute(gemm_tf32_bias,
                             cudaFuncAttributeMaxDynamicSharedMemorySize, GEMM_SMEM);
        attr_set = true;
    }

    dim3 encGrid(HID / 128, (N_NODES + 127) / 128);
    dim3 layGrid(512 / 128, (N_NODES + 127) / 128);
    int nodeWarpBlocks = (N_NODES * 32 + 255) / 256;
    int edgeBlocks = (EPRIME + 255) / 256;
    int edgeHeadBlocks = (EPRIME * 4 + 255) / 256;
    int catBlocks = (HID * 512 + 255) / 256;

    // weight concat + CSR build (independent preamble)
    concat_w_kernel<<<catBlocks, 256>>>(Wl0, Wr0, bl0, br0, wcat0, bcat0);
    concat_w_kernel<<<catBlocks, 256>>>(Wl1, Wr1, bl1, br1, wcat1, bcat1);
    csr_zero_kernel<<<(N_NODES + 255) / 256, 256>>>(deg, cur);
    csr_count_kernel<<<edgeBlocks, 256>>>(ei, deg);
    csr_scan_kernel<<<1, 1024>>>(deg, off);
    csr_fill_kernel<<<edgeBlocks, 256>>>(ei, off, cur, csr);

    // encoder
    gemm_tf32_bias<<<encGrid, 256, GEMM_SMEM>>>(x, enc_W, enc_b, h0, N_NODES, IN_DIM, HID);

    // ----- layer 0 -----
    gemm_tf32_bias<<<layGrid, 256, GEMM_SMEM>>>(h0, wcat0, bcat0, xlr, N_NODES, HID, 512);
    node_layer_kernel<<<nodeWarpBlocks, 256>>>(xlr, h0, att0, bias0, off, csr,
                                               logits, mstat, dstat, h1,
                                               nullptr, nullptr, nullptr);
    alpha_kernel<<<edgeHeadBlocks, 256>>>(ei, logits, mstat, dstat, alpha0);

    // ----- layer 1 -----
    gemm_tf32_bias<<<layGrid, 256, GEMM_SMEM>>>(h1, wcat1, bcat1, xlr, N_NODES, HID, 512);
    node_layer_kernel<<<nodeWarpBlocks, 256>>>(xlr, h1, att1, bias1, off, csr,
                                               logits, mstat, dstat, h2,
                                               clf_W, clf_b, preds);
    alpha_kernel<<<edgeHeadBlocks, 256>>>(ei, logits, mstat, dstat, alpha1);
}